// round 10
// baseline (speedup 1.0000x reference)
#include <cuda_runtime.h>
#include <math.h>

#define BB 4096
#define SS 200
#define DD 64
#define VV 100000
#define ROWF 32   // floats per precomputed row (128B aligned): g[5], q[18], pad

// Static device scratch (allocation-free per harness rules)
__device__ float g_proj[(size_t)VV * ROWF];
__device__ float g_loss[BB];
__device__ unsigned int g_ctr = 0;

__device__ __forceinline__ float fast_tanh(float x) {
    float ax = fabsf(x);
    float t  = __expf(-2.0f * ax);
    float r  = __fdividef(1.0f - t, 1.0f + t);
    return copysignf(r, x);
}

// ---------------------------------------------------------------------------
// Kernel 1: per-vocab precompute (1 row/thread, smem-staged emb).
//   23 dot products of emb_table[v] (64-d) against
//   U = [att_w(5); W0(2);W1(4);W2(4);W3(2);W4(6)].
//   Emb tile (128 rows x 256B) staged coalesced into smem with XOR-16B
//   swizzle; weights broadcast from smem [d][24].
// ---------------------------------------------------------------------------
__global__ void __launch_bounds__(128)
proj_kernel(const float* __restrict__ emb,
            const float* __restrict__ aw,  const float* __restrict__ ab,
            const float* __restrict__ W0,  const float* __restrict__ W1,
            const float* __restrict__ W2,  const float* __restrict__ W3,
            const float* __restrict__ W4) {
    __shared__ float semb[128 * 64];   // staged emb tile, 16B-chunk swizzled
    __shared__ float sw[64 * 24];      // weights [d][j], j 0..23 (23 = pad)
    __shared__ float sab[5];
    const int tid = threadIdx.x;

    // ---- load weights ----
    for (int e = tid; e < 64 * 24; e += 128) {
        int d = e / 24, j = e % 24;
        float val = 0.0f;
        if (j < 5) {
            val = aw[j * 64 + d];
        } else if (j < 23) {
            int jq = j - 5;
            const float* Wsrc; int row;
            if      (jq < 2)  { Wsrc = W0; row = jq;      }
            else if (jq < 6)  { Wsrc = W1; row = jq - 2;  }
            else if (jq < 10) { Wsrc = W2; row = jq - 6;  }
            else if (jq < 12) { Wsrc = W3; row = jq - 10; }
            else              { Wsrc = W4; row = jq - 12; }
            val = Wsrc[row * 64 + d];
        }
        sw[e] = val;
    }
    if (tid < 5) sab[tid] = ab[tid];

    // ---- stage emb tile: 128 rows x 16 chunks(16B), coalesced ----
    const int base = blockIdx.x * 128;
#pragma unroll
    for (int i = 0; i < 16; i++) {
        int q = i * 128 + tid;           // linear chunk id in tile
        int r = q >> 4;                  // local row
        int c = q & 15;                  // chunk within row
        int gr = base + r;
        if (gr >= VV) gr = VV - 1;       // clamp (harmless duplicate read)
        float4 val = *(const float4*)(emb + (size_t)gr * DD + c * 4);
        int sc = c ^ (r & 15);
        *(float4*)(semb + r * 64 + sc * 4) = val;
    }
    __syncthreads();

    const int v = base + tid;
    if (v >= VV) return;

    float acc[23];
#pragma unroll
    for (int j = 0; j < 23; j++) acc[j] = 0.0f;

    const int rsw = tid & 15;
#pragma unroll
    for (int c = 0; c < 16; c++) {
        float4 e4 = *(const float4*)(semb + tid * 64 + ((c ^ rsw) * 4));
        float es[4] = {e4.x, e4.y, e4.z, e4.w};
#pragma unroll
        for (int dd = 0; dd < 4; dd++) {
            float e = es[dd];
            const float4* wr = (const float4*)(sw + (c * 4 + dd) * 24);
#pragma unroll
            for (int q = 0; q < 6; q++) {
                float4 w = wr[q];
                acc[q * 4 + 0] = fmaf(e, w.x, acc[q * 4 + 0]);
                acc[q * 4 + 1] = fmaf(e, w.y, acc[q * 4 + 1]);
                acc[q * 4 + 2] = fmaf(e, w.z, acc[q * 4 + 2]);
                if (q < 5)
                    acc[q * 4 + 3] = fmaf(e, w.w, acc[q * 4 + 3]);
            }
        }
    }

    float o[24];
#pragma unroll
    for (int k = 0; k < 5; k++)
        o[k] = __expf(fast_tanh(acc[k] + sab[k]));
#pragma unroll
    for (int j = 0; j < 18; j++) o[5 + j] = acc[5 + j];
    o[23] = 0.0f;

    float4* op = (float4*)(g_proj + (size_t)v * ROWF);
#pragma unroll
    for (int i = 0; i < 6; i++)
        op[i] = make_float4(o[4 * i], o[4 * i + 1], o[4 * i + 2], o[4 * i + 3]);
}

// ---------------------------------------------------------------------------
// Kernel 2: main fused kernel + fused deterministic loss reduction.
//   Two warps per batch element (100 rows each). Smem-staged indices,
//   register-prefetched gathers, smem-swizzled row staging. Last block
//   (atomic counter) performs the fixed-order loss sum.
// ---------------------------------------------------------------------------
__global__ void __launch_bounds__(128)
main_kernel(const int*   __restrict__ x,
            const float* __restrict__ y,
            float* __restrict__ out, int out_size) {
    __shared__ float stage_all[4][32 * 32];   // per warp: 32 rows x 128B
    __shared__ int   sidx[4][128];            // per warp: chunk indices
    __shared__ float partial[2][24];          // half=1 partials per b-in-block
    __shared__ unsigned int is_last;
    __shared__ float red[128];

    const int lane = threadIdx.x & 31;
    const int warp = threadIdx.x >> 5;
    const int bi   = warp >> 1;               // b within block (0..1)
    const int half = warp & 1;                // seq half (0..1)
    const int b    = blockIdx.x * 2 + bi;
    float* st = stage_all[warp];
    int*   si = sidx[warp];

    // Stage this warp's 100 indices (pad to 128 with 0)
    const int* xb = x + b * SS + half * 100;
#pragma unroll
    for (int c = 0; c < 4; c++) {
        int loc = c * 32 + lane;
        si[loc] = (loc < 100) ? xb[loc] : 0;
    }
    __syncwarp();

    float ls[5] = {0.f, 0.f, 0.f, 0.f, 0.f};
    float acc[18];
#pragma unroll
    for (int j = 0; j < 18; j++) acc[j] = 0.0f;

    const int col = lane & 7;       // 16B column within row (0..7; 0..5 active)
    const int grp = lane >> 3;      // row-within-quad

    float4 buf[8];
    bool   bact[8];

    // Prefetch chunk 0
#pragma unroll
    for (int t = 0; t < 8; t++) {
        int r = t * 4 + grp;
        int v = si[r];
        bact[t] = (col < 6) && (r < 100);
        buf[t] = bact[t] ? *(const float4*)(g_proj + (size_t)v * ROWF + col * 4)
                         : make_float4(0.f, 0.f, 0.f, 0.f);
    }

#pragma unroll
    for (int c = 0; c < 4; c++) {
#pragma unroll
        for (int t = 0; t < 8; t++) {
            int r = t * 4 + grp;
            if (bact[t]) {
                int sc = col ^ (r & 7);
                *(float4*)(st + r * 32 + sc * 4) = buf[t];
            }
        }
        __syncwarp();

        if (c < 3) {
#pragma unroll
            for (int t = 0; t < 8; t++) {
                int r  = t * 4 + grp;
                int gl = (c + 1) * 32 + r;
                int v  = si[gl < 128 ? gl : 0];
                bact[t] = (col < 6) && (gl < 100);
                buf[t] = bact[t] ? *(const float4*)(g_proj + (size_t)v * ROWF + col * 4)
                                 : make_float4(0.f, 0.f, 0.f, 0.f);
            }
        }

        if (c * 32 + lane < 100) {
            const float* rp = st + lane * 32;
            int sw = lane & 7;
            float4 r0 = *(const float4*)(rp + ((0 ^ sw) * 4));
            float4 r1 = *(const float4*)(rp + ((1 ^ sw) * 4));
            float4 r2 = *(const float4*)(rp + ((2 ^ sw) * 4));
            float4 r3 = *(const float4*)(rp + ((3 ^ sw) * 4));
            float4 r4 = *(const float4*)(rp + ((4 ^ sw) * 4));
            float4 r5 = *(const float4*)(rp + ((5 ^ sw) * 4));
            ls[0] += r0.x; ls[1] += r0.y; ls[2] += r0.z; ls[3] += r0.w; ls[4] += r1.x;
            acc[0]  = fmaf(r0.x, r1.y, acc[0]);
            acc[1]  = fmaf(r0.x, r1.z, acc[1]);
            acc[2]  = fmaf(r0.y, r1.w, acc[2]);
            acc[3]  = fmaf(r0.y, r2.x, acc[3]);
            acc[4]  = fmaf(r0.y, r2.y, acc[4]);
            acc[5]  = fmaf(r0.y, r2.z, acc[5]);
            acc[6]  = fmaf(r0.z, r2.w, acc[6]);
            acc[7]  = fmaf(r0.z, r3.x, acc[7]);
            acc[8]  = fmaf(r0.z, r3.y, acc[8]);
            acc[9]  = fmaf(r0.z, r3.z, acc[9]);
            acc[10] = fmaf(r0.w, r3.w, acc[10]);
            acc[11] = fmaf(r0.w, r4.x, acc[11]);
            acc[12] = fmaf(r1.x, r4.y, acc[12]);
            acc[13] = fmaf(r1.x, r4.z, acc[13]);
            acc[14] = fmaf(r1.x, r4.w, acc[14]);
            acc[15] = fmaf(r1.x, r5.x, acc[15]);
            acc[16] = fmaf(r1.x, r5.y, acc[16]);
            acc[17] = fmaf(r1.x, r5.z, acc[17]);
        }
        __syncwarp();
    }

    // ---- intra-warp reductions ----
#pragma unroll
    for (int k = 0; k < 5; k++) {
#pragma unroll
        for (int o = 16; o > 0; o >>= 1)
            ls[k] += __shfl_xor_sync(0xffffffffu, ls[k], o);
    }
#pragma unroll
    for (int j = 0; j < 18; j++) {
#pragma unroll
        for (int o = 16; o > 0; o >>= 1)
            acc[j] += __shfl_xor_sync(0xffffffffu, acc[j], o);
    }

    // ---- combine halves via smem ----
    if (half == 1) {
        if (lane < 5)  partial[bi][lane] = ls[lane];
        if (lane < 18) partial[bi][5 + lane] = acc[lane];
    }
    __syncthreads();

    if (half == 0) {
#pragma unroll
        for (int k = 0; k < 5; k++) ls[k] += partial[bi][k];
#pragma unroll
        for (int j = 0; j < 18; j++) acc[j] += partial[bi][5 + j];

        float inv[5];
#pragma unroll
        for (int k = 0; k < 5; k++) inv[k] = 1.0f / ls[k];

        const int kmap[18] = {0,0, 1,1,1,1, 2,2,2,2, 3,3, 4,4,4,4,4,4};
        float outv[18];
#pragma unroll
        for (int j = 0; j < 18; j++) outv[j] = acc[j] * inv[kmap[j]];

        const float* yb = y + b * 18;
        const int AL[5] = {2, 4, 4, 2, 6};
        float loss = 0.0f;
        float logits[18];
        int base = 0;
#pragma unroll
        for (int i = 0; i < 5; i++) {
            const int L = AL[i];
            float m = outv[base];
#pragma unroll
            for (int jj = 1; jj < L; jj++) m = fmaxf(m, outv[base + jj]);
            float ssum = 0.0f, dy = 0.0f;
#pragma unroll
            for (int jj = 0; jj < L; jj++) {
                float e = __expf(outv[base + jj] - m);
                logits[base + jj] = e;
                ssum += e;
                dy = fmaf(yb[base + jj], outv[base + jj], dy);
            }
            float sinv = 1.0f / ssum;
#pragma unroll
            for (int jj = 0; jj < L; jj++) logits[base + jj] *= sinv;
            loss += m + __logf(ssum) - dy;
            base += L;
        }

        if (lane < 18) out[b * 18 + lane] = logits[lane];
        if (lane == 0) g_loss[b] = loss;
    }

    // ---- fused deterministic loss reduction (last block does it) ----
    __threadfence();
    __syncthreads();
    if (threadIdx.x == 0)
        is_last = (atomicAdd(&g_ctr, 1u) == (unsigned)(gridDim.x - 1));
    __syncthreads();
    if (is_last) {
        if (threadIdx.x == 0) g_ctr = 0;   // reset for next replay
        __threadfence();
        float v = 0.0f;
        for (int i = threadIdx.x; i < BB; i += 128) v += g_loss[i];
        red[threadIdx.x] = v;
        __syncthreads();
        for (int o = 64; o > 0; o >>= 1) {
            if (threadIdx.x < o) red[threadIdx.x] += red[threadIdx.x + o];
            __syncthreads();
        }
        if (threadIdx.x == 0)
            out[out_size - 1] = red[0] * (1.0f / (float)BB);
    }
}

// ---------------------------------------------------------------------------
extern "C" void kernel_launch(void* const* d_in, const int* in_sizes, int n_in,
                              void* d_out, int out_size) {
    const int*   x   = (const int*)  d_in[0];
    const float* y   = (const float*)d_in[1];
    const float* emb = (const float*)d_in[2];
    const float* aw  = (const float*)d_in[3];
    const float* ab  = (const float*)d_in[4];
    const float* W0  = (const float*)d_in[5];
    const float* W1  = (const float*)d_in[6];
    const float* W2  = (const float*)d_in[7];
    const float* W3  = (const float*)d_in[8];
    const float* W4  = (const float*)d_in[9];
    float* out = (float*)d_out;

    proj_kernel<<<(VV + 127) / 128, 128>>>(emb, aw, ab, W0, W1, W2, W3, W4);
    main_kernel<<<BB / 2, 128>>>(x, y, out, out_size);
}

// round 11
// speedup vs baseline: 1.1053x; 1.1053x over previous
#include <cuda_runtime.h>
#include <cuda_fp16.h>
#include <math.h>

#define BB 4096
#define SS 200
#define DD 64
#define VV 100000
#define ROWH 32   // halfs per precomputed row (64B stride): g[5], q[18], pad

// Static device scratch (allocation-free per harness rules)
__device__ __align__(128) __half g_proj[(size_t)VV * ROWH];
__device__ float g_loss[BB];

__device__ __forceinline__ float fast_tanh(float x) {
    float ax = fabsf(x);
    float t  = __expf(-2.0f * ax);
    float r  = __fdividef(1.0f - t, 1.0f + t);
    return copysignf(r, x);
}

// ---------------------------------------------------------------------------
// Kernel 1: per-vocab precompute (1 row/thread, smem-staged emb).
//   23 dot products of emb_table[v] (64-d) against
//   U = [att_w(5); W0(2);W1(4);W2(4);W3(2);W4(6)].
//   Output row v (fp16, 48B payload): [exp(tanh(att+b)) x5, q x18, pad].
// ---------------------------------------------------------------------------
__global__ void __launch_bounds__(128)
proj_kernel(const float* __restrict__ emb,
            const float* __restrict__ aw,  const float* __restrict__ ab,
            const float* __restrict__ W0,  const float* __restrict__ W1,
            const float* __restrict__ W2,  const float* __restrict__ W3,
            const float* __restrict__ W4) {
    __shared__ float semb[128 * 64];   // staged emb tile, 16B-chunk swizzled
    __shared__ float sw[64 * 24];      // weights [d][j], j 0..23 (23 = pad)
    __shared__ float sab[5];
    const int tid = threadIdx.x;

    // ---- load weights ----
    for (int e = tid; e < 64 * 24; e += 128) {
        int d = e / 24, j = e % 24;
        float val = 0.0f;
        if (j < 5) {
            val = aw[j * 64 + d];
        } else if (j < 23) {
            int jq = j - 5;
            const float* Wsrc; int row;
            if      (jq < 2)  { Wsrc = W0; row = jq;      }
            else if (jq < 6)  { Wsrc = W1; row = jq - 2;  }
            else if (jq < 10) { Wsrc = W2; row = jq - 6;  }
            else if (jq < 12) { Wsrc = W3; row = jq - 10; }
            else              { Wsrc = W4; row = jq - 12; }
            val = Wsrc[row * 64 + d];
        }
        sw[e] = val;
    }
    if (tid < 5) sab[tid] = ab[tid];

    // ---- stage emb tile: 128 rows x 16 chunks(16B), coalesced ----
    const int base = blockIdx.x * 128;
#pragma unroll
    for (int i = 0; i < 16; i++) {
        int q = i * 128 + tid;           // linear chunk id in tile
        int r = q >> 4;                  // local row
        int c = q & 15;                  // chunk within row
        int gr = base + r;
        if (gr >= VV) gr = VV - 1;       // clamp (harmless duplicate read)
        float4 val = *(const float4*)(emb + (size_t)gr * DD + c * 4);
        int sc = c ^ (r & 15);
        *(float4*)(semb + r * 64 + sc * 4) = val;
    }
    __syncthreads();

    const int v = base + tid;
    if (v >= VV) return;

    float acc[23];
#pragma unroll
    for (int j = 0; j < 23; j++) acc[j] = 0.0f;

    const int rsw = tid & 15;
#pragma unroll
    for (int c = 0; c < 16; c++) {
        float4 e4 = *(const float4*)(semb + tid * 64 + ((c ^ rsw) * 4));
        float es[4] = {e4.x, e4.y, e4.z, e4.w};
#pragma unroll
        for (int dd = 0; dd < 4; dd++) {
            float e = es[dd];
            const float4* wr = (const float4*)(sw + (c * 4 + dd) * 24);
#pragma unroll
            for (int q = 0; q < 6; q++) {
                float4 w = wr[q];
                acc[q * 4 + 0] = fmaf(e, w.x, acc[q * 4 + 0]);
                acc[q * 4 + 1] = fmaf(e, w.y, acc[q * 4 + 1]);
                acc[q * 4 + 2] = fmaf(e, w.z, acc[q * 4 + 2]);
                if (q < 5)
                    acc[q * 4 + 3] = fmaf(e, w.w, acc[q * 4 + 3]);
            }
        }
    }

    float o[24];
#pragma unroll
    for (int k = 0; k < 5; k++)
        o[k] = __expf(fast_tanh(acc[k] + sab[k]));
#pragma unroll
    for (int j = 0; j < 18; j++) o[5 + j] = acc[5 + j];
    o[23] = 0.0f;

    // pack to fp16: 24 halfs = 48B = 3x16B stores
    __half2 hp[12];
#pragma unroll
    for (int i = 0; i < 12; i++)
        hp[i] = __floats2half2_rn(o[2 * i], o[2 * i + 1]);
    const uint4* hp4 = (const uint4*)hp;
    uint4* op = (uint4*)(g_proj + (size_t)v * ROWH);
    op[0] = hp4[0];
    op[1] = hp4[1];
    op[2] = hp4[2];
}

// ---------------------------------------------------------------------------
// Kernel 2: main fused kernel. TWO warps per batch element (100 rows each,
// 4 chunks of 32). fp16 rows: 48B payload gathered by 4-lane groups
// (8 rows per LDG.128), staged in smem with 80B row stride (20 floats) ->
// conflict-free without swizzle. Register prefetch across chunks.
// ---------------------------------------------------------------------------
__global__ void __launch_bounds__(128)
main_kernel(const int*   __restrict__ x,
            const float* __restrict__ y,
            float* __restrict__ out) {
    __shared__ float stage_all[4][32 * 20];   // per warp: 32 rows x 80B
    __shared__ int   sidx[4][128];            // per warp: chunk indices
    __shared__ float partial[2][24];          // half=1 partials per b-in-block

    const int lane = threadIdx.x & 31;
    const int warp = threadIdx.x >> 5;
    const int bi   = warp >> 1;               // b within block (0..1)
    const int half = warp & 1;                // seq half (0..1)
    const int b    = blockIdx.x * 2 + bi;
    float* st = stage_all[warp];
    int*   si = sidx[warp];

    // Stage this warp's 100 indices (pad to 128 with 0)
    const int* xb = x + b * SS + half * 100;
#pragma unroll
    for (int c = 0; c < 4; c++) {
        int loc = c * 32 + lane;
        si[loc] = (loc < 100) ? xb[loc] : 0;
    }
    __syncwarp();

    float ls[5] = {0.f, 0.f, 0.f, 0.f, 0.f};
    float acc[18];
#pragma unroll
    for (int j = 0; j < 18; j++) acc[j] = 0.0f;

    const int col = lane & 3;       // 16B chunk within row (0..3; 0..2 active)
    const int grp = lane >> 2;      // row slot (0..7)

    float4 buf[4];
    bool   bact[4];

    // Prefetch chunk 0 (rows r = t*8+grp)
#pragma unroll
    for (int t = 0; t < 4; t++) {
        int r = t * 8 + grp;
        int v = si[r];
        bact[t] = (col < 3) && (r < 100);
        buf[t] = bact[t]
            ? *(const float4*)(g_proj + (size_t)v * ROWH + col * 8)
            : make_float4(0.f, 0.f, 0.f, 0.f);
    }

#pragma unroll
    for (int c = 0; c < 4; c++) {
        // Store prefetched chunk into smem (80B row stride, no swizzle)
#pragma unroll
        for (int t = 0; t < 4; t++) {
            int r = t * 8 + grp;
            if (bact[t])
                *(float4*)(st + r * 20 + col * 4) = buf[t];
        }
        __syncwarp();

        // Prefetch next chunk (LDGs in flight during compute below)
        if (c < 3) {
#pragma unroll
            for (int t = 0; t < 4; t++) {
                int r  = t * 8 + grp;
                int gl = (c + 1) * 32 + r;
                int v  = si[gl < 128 ? gl : 0];
                bact[t] = (col < 3) && (gl < 100);
                buf[t] = bact[t]
                    ? *(const float4*)(g_proj + (size_t)v * ROWH + col * 8)
                    : make_float4(0.f, 0.f, 0.f, 0.f);
            }
        }

        // Compute: lane consumes row `lane` of current chunk
        if (c * 32 + lane < 100) {
            const float* rp = st + lane * 20;
            float4 c0 = *(const float4*)(rp + 0);
            float4 c1 = *(const float4*)(rp + 4);
            float4 c2 = *(const float4*)(rp + 8);
            float4 cs[3] = {c0, c1, c2};
            const __half2* h2 = (const __half2*)cs;   // 12 half2 = 24 halfs
            float z[24];
#pragma unroll
            for (int i = 0; i < 12; i++) {
                float2 f = __half22float2(h2[i]);
                z[2 * i]     = f.x;
                z[2 * i + 1] = f.y;
            }
            // z[0..4] = g, z[5..22] = q
            ls[0] += z[0]; ls[1] += z[1]; ls[2] += z[2]; ls[3] += z[3]; ls[4] += z[4];
            const int kmap[18] = {0,0, 1,1,1,1, 2,2,2,2, 3,3, 4,4,4,4,4,4};
#pragma unroll
            for (int j = 0; j < 18; j++)
                acc[j] = fmaf(z[kmap[j]], z[5 + j], acc[j]);
        }
        __syncwarp();
    }

    // ---- intra-warp reductions ----
#pragma unroll
    for (int k = 0; k < 5; k++) {
#pragma unroll
        for (int o = 16; o > 0; o >>= 1)
            ls[k] += __shfl_xor_sync(0xffffffffu, ls[k], o);
    }
#pragma unroll
    for (int j = 0; j < 18; j++) {
#pragma unroll
        for (int o = 16; o > 0; o >>= 1)
            acc[j] += __shfl_xor_sync(0xffffffffu, acc[j], o);
    }

    // ---- combine halves via smem ----
    if (half == 1) {
        if (lane < 5)  partial[bi][lane] = ls[lane];
        if (lane < 18) partial[bi][5 + lane] = acc[lane];
    }
    __syncthreads();
    if (half == 1) return;

#pragma unroll
    for (int k = 0; k < 5; k++) ls[k] += partial[bi][k];
#pragma unroll
    for (int j = 0; j < 18; j++) acc[j] += partial[bi][5 + j];

    float inv[5];
#pragma unroll
    for (int k = 0; k < 5; k++) inv[k] = 1.0f / ls[k];

    const int kmap[18] = {0,0, 1,1,1,1, 2,2,2,2, 3,3, 4,4,4,4,4,4};
    float outv[18];
#pragma unroll
    for (int j = 0; j < 18; j++) outv[j] = acc[j] * inv[kmap[j]];

    // ---- per-group softmax + cross-entropy loss ----
    const float* yb = y + b * 18;
    const int AL[5] = {2, 4, 4, 2, 6};
    float loss = 0.0f;
    float logits[18];
    int base = 0;
#pragma unroll
    for (int i = 0; i < 5; i++) {
        const int L = AL[i];
        float m = outv[base];
#pragma unroll
        for (int jj = 1; jj < L; jj++) m = fmaxf(m, outv[base + jj]);
        float ssum = 0.0f, dy = 0.0f;
#pragma unroll
        for (int jj = 0; jj < L; jj++) {
            float e = __expf(outv[base + jj] - m);
            logits[base + jj] = e;
            ssum += e;
            dy = fmaf(yb[base + jj], outv[base + jj], dy);
        }
        float sinv = 1.0f / ssum;
#pragma unroll
        for (int jj = 0; jj < L; jj++) logits[base + jj] *= sinv;
        loss += m + __logf(ssum) - dy;
        base += L;
    }

    if (lane < 18) out[b * 18 + lane] = logits[lane];
    if (lane == 0) g_loss[b] = loss;
}

// ---------------------------------------------------------------------------
// Kernel 3: deterministic loss reduction
// ---------------------------------------------------------------------------
__global__ void loss_reduce(float* __restrict__ out_loss) {
    __shared__ float s[256];
    float v = 0.0f;
    for (int i = threadIdx.x; i < BB; i += 256) v += g_loss[i];
    s[threadIdx.x] = v;
    __syncthreads();
    for (int o = 128; o > 0; o >>= 1) {
        if (threadIdx.x < o) s[threadIdx.x] += s[threadIdx.x + o];
        __syncthreads();
    }
    if (threadIdx.x == 0) *out_loss = s[0] * (1.0f / (float)BB);
}

// ---------------------------------------------------------------------------
extern "C" void kernel_launch(void* const* d_in, const int* in_sizes, int n_in,
                              void* d_out, int out_size) {
    const int*   x   = (const int*)  d_in[0];
    const float* y   = (const float*)d_in[1];
    const float* emb = (const float*)d_in[2];
    const float* aw  = (const float*)d_in[3];
    const float* ab  = (const float*)d_in[4];
    const float* W0  = (const float*)d_in[5];
    const float* W1  = (const float*)d_in[6];
    const float* W2  = (const float*)d_in[7];
    const float* W3  = (const float*)d_in[8];
    const float* W4  = (const float*)d_in[9];
    float* out = (float*)d_out;

    proj_kernel<<<(VV + 127) / 128, 128>>>(emb, aw, ab, W0, W1, W2, W3, W4);
    main_kernel<<<BB / 2, 128>>>(x, y, out);
    loss_reduce<<<1, 256>>>(out + (out_size - 1));
}

// round 12
// speedup vs baseline: 1.5555x; 1.4073x over previous
#include <cuda_runtime.h>
#include <cuda_fp16.h>
#include <math.h>

#define BB 4096
#define SS 200
#define DD 64
#define VV 100000
#define ROWH 32      // halfs per g_proj row (64B stride): g[5], q[18], pad
#define ASTRIDE 72   // halfs per staged smem row (144B) -> conflict-free frags

// Static device scratch (allocation-free per harness rules)
__device__ __align__(128) __half g_proj[(size_t)VV * ROWH];
__device__ float g_loss[BB];

__device__ __forceinline__ float fast_tanh(float x) {
    float ax = fabsf(x);
    float t  = __expf(-2.0f * ax);
    float r  = __fdividef(1.0f - t, 1.0f + t);
    return copysignf(r, x);
}

__device__ __forceinline__ void mma_16816(float* c, const unsigned* a, const unsigned* b) {
    asm volatile(
        "mma.sync.aligned.m16n8k16.row.col.f32.f16.f16.f32 "
        "{%0,%1,%2,%3}, {%4,%5,%6,%7}, {%8,%9}, {%0,%1,%2,%3};\n"
        : "+f"(c[0]), "+f"(c[1]), "+f"(c[2]), "+f"(c[3])
        : "r"(a[0]), "r"(a[1]), "r"(a[2]), "r"(a[3]), "r"(b[0]), "r"(b[1]));
}

// ---------------------------------------------------------------------------
// Kernel 1: per-vocab precompute via tensor cores.
//   C[128x24 per block] = emb_tile[128x64] @ U^T[64x24],
//   U = [att_w(5); W0(2);W1(4);W2(4);W3(2);W4(6); zero-pad(1)].
//   Block = 256 threads (8 warps x 16 rows). A/B fragments loaded directly
//   from smem (144B row stride -> conflict-free LDS.32).
//   Epilogue: j<5 -> exp(tanh(.+b)); pack fp16 rows of g_proj.
// ---------------------------------------------------------------------------
__global__ void __launch_bounds__(256)
proj_kernel(const float* __restrict__ emb,
            const float* __restrict__ aw,  const float* __restrict__ ab,
            const float* __restrict__ W0,  const float* __restrict__ W1,
            const float* __restrict__ W2,  const float* __restrict__ W3,
            const float* __restrict__ W4) {
    __shared__ __half semb[128 * ASTRIDE];   // 18432 B
    __shared__ __half sU[24 * ASTRIDE];      //  3456 B
    __shared__ float  sab[5];
    const int tid  = threadIdx.x;
    const int lane = tid & 31;
    const int wid  = tid >> 5;

    // ---- stage U (weights) as fp16: rows j=0..22, row 23 = 0 ----
    for (int e = tid; e < 24 * 64; e += 256) {
        int j = e >> 6, d = e & 63;
        float val = 0.0f;
        if (j < 5) {
            val = aw[j * 64 + d];
        } else if (j < 23) {
            int jq = j - 5;
            const float* Wsrc; int row;
            if      (jq < 2)  { Wsrc = W0; row = jq;      }
            else if (jq < 6)  { Wsrc = W1; row = jq - 2;  }
            else if (jq < 10) { Wsrc = W2; row = jq - 6;  }
            else if (jq < 12) { Wsrc = W3; row = jq - 10; }
            else              { Wsrc = W4; row = jq - 12; }
            val = Wsrc[row * 64 + d];
        }
        sU[j * ASTRIDE + d] = __float2half(val);
    }
    if (tid < 5) sab[tid] = ab[tid];

    // ---- stage emb tile: 128 rows x 16 float4-chunks, coalesced, cvt fp16 ----
    const int base = blockIdx.x * 128;
#pragma unroll
    for (int i = 0; i < 8; i++) {
        int q = i * 256 + tid;           // chunk id in tile
        int r = q >> 4;                  // local row
        int c = q & 15;                  // float4 chunk within row
        int gr = base + r;
        if (gr >= VV) gr = VV - 1;       // clamp (duplicate read, stores guarded)
        float4 v4 = *(const float4*)(emb + (size_t)gr * DD + c * 4);
        __half2 h0 = __floats2half2_rn(v4.x, v4.y);
        __half2 h1 = __floats2half2_rn(v4.z, v4.w);
        uint2 pk = make_uint2(*(unsigned*)&h0, *(unsigned*)&h1);
        *(uint2*)(semb + r * ASTRIDE + c * 4) = pk;   // 8B store, conflict-free
    }
    __syncthreads();

    // ---- load B fragments (shared by all warps) into registers ----
    unsigned bfr[3][4][2];
    {
        const int bn = lane >> 2;        // column n within tile
        const int bk = (lane & 3) * 2;   // k-pair
#pragma unroll
        for (int nt = 0; nt < 3; nt++) {
            int n = nt * 8 + bn;
#pragma unroll
            for (int kt = 0; kt < 4; kt++) {
                bfr[nt][kt][0] = *(const unsigned*)(sU + n * ASTRIDE + kt * 16 + bk);
                bfr[nt][kt][1] = *(const unsigned*)(sU + n * ASTRIDE + kt * 16 + 8 + bk);
            }
        }
    }

    // ---- MMA: warp computes rows [wid*16, wid*16+16) ----
    const int mrow = wid * 16 + (lane >> 2);
    const int ak   = (lane & 3) * 2;
    float cacc[3][4];
#pragma unroll
    for (int nt = 0; nt < 3; nt++)
#pragma unroll
        for (int i = 0; i < 4; i++) cacc[nt][i] = 0.0f;

#pragma unroll
    for (int kt = 0; kt < 4; kt++) {
        unsigned a[4];
        a[0] = *(const unsigned*)(semb + mrow * ASTRIDE + kt * 16 + ak);
        a[1] = *(const unsigned*)(semb + (mrow + 8) * ASTRIDE + kt * 16 + ak);
        a[2] = *(const unsigned*)(semb + mrow * ASTRIDE + kt * 16 + 8 + ak);
        a[3] = *(const unsigned*)(semb + (mrow + 8) * ASTRIDE + kt * 16 + 8 + ak);
#pragma unroll
        for (int nt = 0; nt < 3; nt++)
            mma_16816(cacc[nt], a, bfr[nt][kt]);
    }

    // ---- epilogue: transform j<5, pack fp16, store ----
    const int vbase = base + wid * 16 + (lane >> 2);
#pragma unroll
    for (int h = 0; h < 2; h++) {
        int v = vbase + h * 8;
        if (v < VV) {
#pragma unroll
            for (int nt = 0; nt < 3; nt++) {
                int j0 = nt * 8 + (lane & 3) * 2;
                float x0 = cacc[nt][h * 2 + 0];
                float x1 = cacc[nt][h * 2 + 1];
                if (j0 < 5)     x0 = __expf(fast_tanh(x0 + sab[j0]));
                if (j0 + 1 < 5) x1 = __expf(fast_tanh(x1 + sab[j0 + 1]));
                __half2 hv = __floats2half2_rn(x0, x1);
                *(__half2*)(g_proj + (size_t)v * ROWH + j0) = hv;
            }
        }
    }
}

// ---------------------------------------------------------------------------
// Kernel 2: main fused kernel (unchanged from R11). Two warps per batch
// element; fp16 rows gathered by 4-lane groups, staged with 80B stride.
// ---------------------------------------------------------------------------
__global__ void __launch_bounds__(128)
main_kernel(const int*   __restrict__ x,
            const float* __restrict__ y,
            float* __restrict__ out) {
    __shared__ float stage_all[4][32 * 20];
    __shared__ int   sidx[4][128];
    __shared__ float partial[2][24];

    const int lane = threadIdx.x & 31;
    const int warp = threadIdx.x >> 5;
    const int bi   = warp >> 1;
    const int half = warp & 1;
    const int b    = blockIdx.x * 2 + bi;
    float* st = stage_all[warp];
    int*   si = sidx[warp];

    const int* xb = x + b * SS + half * 100;
#pragma unroll
    for (int c = 0; c < 4; c++) {
        int loc = c * 32 + lane;
        si[loc] = (loc < 100) ? xb[loc] : 0;
    }
    __syncwarp();

    float ls[5] = {0.f, 0.f, 0.f, 0.f, 0.f};
    float acc[18];
#pragma unroll
    for (int j = 0; j < 18; j++) acc[j] = 0.0f;

    const int col = lane & 3;
    const int grp = lane >> 2;

    float4 buf[4];
    bool   bact[4];

#pragma unroll
    for (int t = 0; t < 4; t++) {
        int r = t * 8 + grp;
        int v = si[r];
        bact[t] = (col < 3) && (r < 100);
        buf[t] = bact[t]
            ? *(const float4*)(g_proj + (size_t)v * ROWH + col * 8)
            : make_float4(0.f, 0.f, 0.f, 0.f);
    }

#pragma unroll
    for (int c = 0; c < 4; c++) {
#pragma unroll
        for (int t = 0; t < 4; t++) {
            int r = t * 8 + grp;
            if (bact[t])
                *(float4*)(st + r * 20 + col * 4) = buf[t];
        }
        __syncwarp();

        if (c < 3) {
#pragma unroll
            for (int t = 0; t < 4; t++) {
                int r  = t * 8 + grp;
                int gl = (c + 1) * 32 + r;
                int v  = si[gl < 128 ? gl : 0];
                bact[t] = (col < 3) && (gl < 100);
                buf[t] = bact[t]
                    ? *(const float4*)(g_proj + (size_t)v * ROWH + col * 8)
                    : make_float4(0.f, 0.f, 0.f, 0.f);
            }
        }

        if (c * 32 + lane < 100) {
            const float* rp = st + lane * 20;
            float4 c0 = *(const float4*)(rp + 0);
            float4 c1 = *(const float4*)(rp + 4);
            float4 c2 = *(const float4*)(rp + 8);
            float4 cs[3] = {c0, c1, c2};
            const __half2* h2 = (const __half2*)cs;
            float z[24];
#pragma unroll
            for (int i = 0; i < 12; i++) {
                float2 f = __half22float2(h2[i]);
                z[2 * i]     = f.x;
                z[2 * i + 1] = f.y;
            }
            ls[0] += z[0]; ls[1] += z[1]; ls[2] += z[2]; ls[3] += z[3]; ls[4] += z[4];
            const int kmap[18] = {0,0, 1,1,1,1, 2,2,2,2, 3,3, 4,4,4,4,4,4};
#pragma unroll
            for (int j = 0; j < 18; j++)
                acc[j] = fmaf(z[kmap[j]], z[5 + j], acc[j]);
        }
        __syncwarp();
    }

#pragma unroll
    for (int k = 0; k < 5; k++) {
#pragma unroll
        for (int o = 16; o > 0; o >>= 1)
            ls[k] += __shfl_xor_sync(0xffffffffu, ls[k], o);
    }
#pragma unroll
    for (int j = 0; j < 18; j++) {
#pragma unroll
        for (int o = 16; o > 0; o >>= 1)
            acc[j] += __shfl_xor_sync(0xffffffffu, acc[j], o);
    }

    if (half == 1) {
        if (lane < 5)  partial[bi][lane] = ls[lane];
        if (lane < 18) partial[bi][5 + lane] = acc[lane];
    }
    __syncthreads();
    if (half == 1) return;

#pragma unroll
    for (int k = 0; k < 5; k++) ls[k] += partial[bi][k];
#pragma unroll
    for (int j = 0; j < 18; j++) acc[j] += partial[bi][5 + j];

    float inv[5];
#pragma unroll
    for (int k = 0; k < 5; k++) inv[k] = 1.0f / ls[k];

    const int kmap[18] = {0,0, 1,1,1,1, 2,2,2,2, 3,3, 4,4,4,4,4,4};
    float outv[18];
#pragma unroll
    for (int j = 0; j < 18; j++) outv[j] = acc[j] * inv[kmap[j]];

    const float* yb = y + b * 18;
    const int AL[5] = {2, 4, 4, 2, 6};
    float loss = 0.0f;
    float logits[18];
    int base = 0;
#pragma unroll
    for (int i = 0; i < 5; i++) {
        const int L = AL[i];
        float m = outv[base];
#pragma unroll
        for (int jj = 1; jj < L; jj++) m = fmaxf(m, outv[base + jj]);
        float ssum = 0.0f, dy = 0.0f;
#pragma unroll
        for (int jj = 0; jj < L; jj++) {
            float e = __expf(outv[base + jj] - m);
            logits[base + jj] = e;
            ssum += e;
            dy = fmaf(yb[base + jj], outv[base + jj], dy);
        }
        float sinv = 1.0f / ssum;
#pragma unroll
        for (int jj = 0; jj < L; jj++) logits[base + jj] *= sinv;
        loss += m + __logf(ssum) - dy;
        base += L;
    }

    if (lane < 18) out[b * 18 + lane] = logits[lane];
    if (lane == 0) g_loss[b] = loss;
}

// ---------------------------------------------------------------------------
// Kernel 3: deterministic loss reduction
// ---------------------------------------------------------------------------
__global__ void loss_reduce(float* __restrict__ out_loss) {
    __shared__ float s[256];
    float v = 0.0f;
    for (int i = threadIdx.x; i < BB; i += 256) v += g_loss[i];
    s[threadIdx.x] = v;
    __syncthreads();
    for (int o = 128; o > 0; o >>= 1) {
        if (threadIdx.x < o) s[threadIdx.x] += s[threadIdx.x + o];
        __syncthreads();
    }
    if (threadIdx.x == 0) *out_loss = s[0] * (1.0f / (float)BB);
}

// ---------------------------------------------------------------------------
extern "C" void kernel_launch(void* const* d_in, const int* in_sizes, int n_in,
                              void* d_out, int out_size) {
    const int*   x   = (const int*)  d_in[0];
    const float* y   = (const float*)d_in[1];
    const float* emb = (const float*)d_in[2];
    const float* aw  = (const float*)d_in[3];
    const float* ab  = (const float*)d_in[4];
    const float* W0  = (const float*)d_in[5];
    const float* W1  = (const float*)d_in[6];
    const float* W2  = (const float*)d_in[7];
    const float* W3  = (const float*)d_in[8];
    const float* W4  = (const float*)d_in[9];
    float* out = (float*)d_out;

    proj_kernel<<<(VV + 127) / 128, 256>>>(emb, aw, ab, W0, W1, W2, W3, W4);
    main_kernel<<<BB / 2, 128>>>(x, y, out);
    loss_reduce<<<1, 256>>>(out + (out_size - 1));
}

// round 14
// speedup vs baseline: 1.6950x; 1.0897x over previous
#include <cuda_runtime.h>
#include <cuda_fp16.h>
#include <math.h>

#define BB 4096
#define SS 200
#define DD 64
#define VV 100000
#define ROWH 32      // halfs per g_proj row (64B stride): g[5], q[18], pad
#define ASTRIDE 72   // halfs per staged smem row (144B) -> conflict-free frags

// Static device scratch (allocation-free per harness rules)
__device__ __align__(128) __half g_proj[(size_t)VV * ROWH];
__device__ float g_loss[BB];

__device__ __forceinline__ float fast_tanh(float x) {
    float ax = fabsf(x);
    float t  = __expf(-2.0f * ax);
    float r  = __fdividef(1.0f - t, 1.0f + t);
    return copysignf(r, x);
}

__device__ __forceinline__ void mma_16816(float* c, const unsigned* a, const unsigned* b) {
    asm volatile(
        "mma.sync.aligned.m16n8k16.row.col.f32.f16.f16.f32 "
        "{%0,%1,%2,%3}, {%4,%5,%6,%7}, {%8,%9}, {%0,%1,%2,%3};\n"
        : "+f"(c[0]), "+f"(c[1]), "+f"(c[2]), "+f"(c[3])
        : "r"(a[0]), "r"(a[1]), "r"(a[2]), "r"(a[3]), "r"(b[0]), "r"(b[1]));
}

// ---------------------------------------------------------------------------
// Kernel 1: per-vocab precompute via tensor cores. 64 rows per block,
// 128 threads (4 warps x 16 rows) -> ~10.6 independent blocks resident per
// SM (one wave, full DRAM-latency overlap).
// ---------------------------------------------------------------------------
__global__ void __launch_bounds__(128)
proj_kernel(const float* __restrict__ emb,
            const float* __restrict__ aw,  const float* __restrict__ ab,
            const float* __restrict__ W0,  const float* __restrict__ W1,
            const float* __restrict__ W2,  const float* __restrict__ W3,
            const float* __restrict__ W4) {
    __shared__ __half semb[64 * ASTRIDE];    // 9216 B
    __shared__ __half sU[24 * ASTRIDE];      // 3456 B
    __shared__ float  sab[5];
    const int tid  = threadIdx.x;
    const int lane = tid & 31;
    const int wid  = tid >> 5;

    // ---- stage U (weights) as fp16: rows j=0..22, row 23 = 0 ----
    for (int e = tid; e < 24 * 64; e += 128) {
        int j = e >> 6, d = e & 63;
        float val = 0.0f;
        if (j < 5) {
            val = aw[j * 64 + d];
        } else if (j < 23) {
            int jq = j - 5;
            const float* Wsrc; int row;
            if      (jq < 2)  { Wsrc = W0; row = jq;      }
            else if (jq < 6)  { Wsrc = W1; row = jq - 2;  }
            else if (jq < 10) { Wsrc = W2; row = jq - 6;  }
            else if (jq < 12) { Wsrc = W3; row = jq - 10; }
            else              { Wsrc = W4; row = jq - 12; }
            val = Wsrc[row * 64 + d];
        }
        sU[j * ASTRIDE + d] = __float2half(val);
    }
    if (tid < 5) sab[tid] = ab[tid];

    // ---- stage emb tile: 64 rows x 16 float4-chunks, coalesced, cvt fp16 ----
    const int base = blockIdx.x * 64;
#pragma unroll
    for (int i = 0; i < 8; i++) {
        int q = i * 128 + tid;           // chunk id in tile (0..1023)
        int r = q >> 4;                  // local row
        int c = q & 15;                  // float4 chunk within row
        int gr = base + r;
        if (gr >= VV) gr = VV - 1;       // clamp (duplicate read, stores guarded)
        float4 v4 = *(const float4*)(emb + (size_t)gr * DD + c * 4);
        __half2 h0 = __floats2half2_rn(v4.x, v4.y);
        __half2 h1 = __floats2half2_rn(v4.z, v4.w);
        uint2 pk = make_uint2(*(unsigned*)&h0, *(unsigned*)&h1);
        *(uint2*)(semb + r * ASTRIDE + c * 4) = pk;
    }
    __syncthreads();

    // ---- load B fragments into registers ----
    unsigned bfr[3][4][2];
    {
        const int bn = lane >> 2;
        const int bk = (lane & 3) * 2;
#pragma unroll
        for (int nt = 0; nt < 3; nt++) {
            int n = nt * 8 + bn;
#pragma unroll
            for (int kt = 0; kt < 4; kt++) {
                bfr[nt][kt][0] = *(const unsigned*)(sU + n * ASTRIDE + kt * 16 + bk);
                bfr[nt][kt][1] = *(const unsigned*)(sU + n * ASTRIDE + kt * 16 + 8 + bk);
            }
        }
    }

    // ---- MMA: warp computes rows [wid*16, wid*16+16) ----
    const int mrow = wid * 16 + (lane >> 2);
    const int ak   = (lane & 3) * 2;
    float cacc[3][4];
#pragma unroll
    for (int nt = 0; nt < 3; nt++)
#pragma unroll
        for (int i = 0; i < 4; i++) cacc[nt][i] = 0.0f;

#pragma unroll
    for (int kt = 0; kt < 4; kt++) {
        unsigned a[4];
        a[0] = *(const unsigned*)(semb + mrow * ASTRIDE + kt * 16 + ak);
        a[1] = *(const unsigned*)(semb + (mrow + 8) * ASTRIDE + kt * 16 + ak);
        a[2] = *(const unsigned*)(semb + mrow * ASTRIDE + kt * 16 + 8 + ak);
        a[3] = *(const unsigned*)(semb + (mrow + 8) * ASTRIDE + kt * 16 + 8 + ak);
#pragma unroll
        for (int nt = 0; nt < 3; nt++)
            mma_16816(cacc[nt], a, bfr[nt][kt]);
    }

    // ---- epilogue: transform j<5, pack fp16, store ----
    const int vbase = base + wid * 16 + (lane >> 2);
#pragma unroll
    for (int h = 0; h < 2; h++) {
        int v = vbase + h * 8;
        if (v < VV) {
#pragma unroll
            for (int nt = 0; nt < 3; nt++) {
                int j0 = nt * 8 + (lane & 3) * 2;
                float x0 = cacc[nt][h * 2 + 0];
                float x1 = cacc[nt][h * 2 + 1];
                if (j0 < 5)     x0 = __expf(fast_tanh(x0 + sab[j0]));
                if (j0 + 1 < 5) x1 = __expf(fast_tanh(x1 + sab[j0 + 1]));
                __half2 hv = __floats2half2_rn(x0, x1);
                *(__half2*)(g_proj + (size_t)v * ROWH + j0) = hv;
            }
        }
    }
}

// ---------------------------------------------------------------------------
// Kernel 2: main fused kernel. Two warps per batch element (100 rows each).
// ALL 300 16B gather chunks per warp issued upfront via cp.async (LDGSTS:
// no register cost, MLP ~10/lane), single wait, then straight-line compute
// over 100 rows from smem (80B row stride -> conflict-free LDS.128).
// ---------------------------------------------------------------------------
__global__ void __launch_bounds__(128, 8)
main_kernel(const int*   __restrict__ x,
            const float* __restrict__ y,
            float* __restrict__ out) {
    __shared__ float stage_all[4][100 * 20];  // per warp: 100 rows x 80B
    __shared__ int   sidx[4][128];
    __shared__ float partial[2][24];

    const int lane = threadIdx.x & 31;
    const int warp = threadIdx.x >> 5;
    const int bi   = warp >> 1;
    const int half = warp & 1;
    const int b    = blockIdx.x * 2 + bi;
    float* st = stage_all[warp];
    int*   si = sidx[warp];

    // Stage this warp's 100 indices
    const int* xb = x + b * SS + half * 100;
#pragma unroll
    for (int c = 0; c < 4; c++) {
        int loc = c * 32 + lane;
        si[loc] = (loc < 100) ? xb[loc] : 0;
    }
    __syncwarp();

    // ---- issue all 300 gather copies (cp.async 16B each) ----
#pragma unroll
    for (int i = 0; i < 10; i++) {
        int id = i * 32 + lane;
        if (id < 300) {
            int row = id / 3;
            int ch  = id - row * 3;
            int v   = si[row];
            const __half* src = g_proj + (size_t)v * ROWH + ch * 8;
            unsigned dst = (unsigned)__cvta_generic_to_shared(st + row * 20 + ch * 4);
            asm volatile("cp.async.cg.shared.global [%0], [%1], 16;\n"
                         :: "r"(dst), "l"(src) : "memory");
        }
    }
    asm volatile("cp.async.commit_group;\n" ::: "memory");
    asm volatile("cp.async.wait_group 0;\n" ::: "memory");
    __syncthreads();   // publish async-stored smem to all lanes

    float ls[5] = {0.f, 0.f, 0.f, 0.f, 0.f};
    float acc[18];
#pragma unroll
    for (int j = 0; j < 18; j++) acc[j] = 0.0f;

    // ---- compute: lane consumes rows lane, lane+32, lane+64, lane+96 ----
#pragma unroll
    for (int it = 0; it < 4; it++) {
        int row = it * 32 + lane;
        if (row < 100) {
            const float* rp = st + row * 20;
            float4 cs[3];
            cs[0] = *(const float4*)(rp + 0);
            cs[1] = *(const float4*)(rp + 4);
            cs[2] = *(const float4*)(rp + 8);
            const __half2* h2 = (const __half2*)cs;
            float2 p[12];
#pragma unroll
            for (int i = 0; i < 12; i++) p[i] = __half22float2(h2[i]);
            // p: (g0,g1)(g2,g3)(g4,q0)(q1,q2)(q3,q4)(q5,q6)(q7,q8)(q9,q10)
            //    (q11,q12)(q13,q14)(q15,q16)(q17,pad)
            ls[0] += p[0].x; ls[1] += p[0].y; ls[2] += p[1].x;
            ls[3] += p[1].y; ls[4] += p[2].x;
            acc[0]  = fmaf(p[0].x, p[2].y, acc[0]);
            acc[1]  = fmaf(p[0].x, p[3].x, acc[1]);
            acc[2]  = fmaf(p[0].y, p[3].y, acc[2]);
            acc[3]  = fmaf(p[0].y, p[4].x, acc[3]);
            acc[4]  = fmaf(p[0].y, p[4].y, acc[4]);
            acc[5]  = fmaf(p[0].y, p[5].x, acc[5]);
            acc[6]  = fmaf(p[1].x, p[5].y, acc[6]);
            acc[7]  = fmaf(p[1].x, p[6].x, acc[7]);
            acc[8]  = fmaf(p[1].x, p[6].y, acc[8]);
            acc[9]  = fmaf(p[1].x, p[7].x, acc[9]);
            acc[10] = fmaf(p[1].y, p[7].y, acc[10]);
            acc[11] = fmaf(p[1].y, p[8].x, acc[11]);
            acc[12] = fmaf(p[2].x, p[8].y, acc[12]);
            acc[13] = fmaf(p[2].x, p[9].x, acc[13]);
            acc[14] = fmaf(p[2].x, p[9].y, acc[14]);
            acc[15] = fmaf(p[2].x, p[10].x, acc[15]);
            acc[16] = fmaf(p[2].x, p[10].y, acc[16]);
            acc[17] = fmaf(p[2].x, p[11].x, acc[17]);
        }
    }

    // ---- intra-warp reductions ----
#pragma unroll
    for (int k = 0; k < 5; k++) {
#pragma unroll
        for (int o = 16; o > 0; o >>= 1)
            ls[k] += __shfl_xor_sync(0xffffffffu, ls[k], o);
    }
#pragma unroll
    for (int j = 0; j < 18; j++) {
#pragma unroll
        for (int o = 16; o > 0; o >>= 1)
            acc[j] += __shfl_xor_sync(0xffffffffu, acc[j], o);
    }

    // ---- combine halves via smem ----
    if (half == 1) {
        if (lane < 5)  partial[bi][lane] = ls[lane];
        if (lane < 18) partial[bi][5 + lane] = acc[lane];
    }
    __syncthreads();
    if (half == 1) return;

#pragma unroll
    for (int k = 0; k < 5; k++) ls[k] += partial[bi][k];
#pragma unroll
    for (int j = 0; j < 18; j++) acc[j] += partial[bi][5 + j];

    float inv[5];
#pragma unroll
    for (int k = 0; k < 5; k++) inv[k] = 1.0f / ls[k];

    const int kmap[18] = {0,0, 1,1,1,1, 2,2,2,2, 3,3, 4,4,4,4,4,4};
    float outv[18];
#pragma unroll
    for (int j = 0; j < 18; j++) outv[j] = acc[j] * inv[kmap[j]];

    // ---- per-group softmax + cross-entropy loss ----
    const float* yb = y + b * 18;
    const int AL[5] = {2, 4, 4, 2, 6};
    float loss = 0.0f;
    float logits[18];
    int base = 0;
#pragma unroll
    for (int i = 0; i < 5; i++) {
        const int L = AL[i];
        float m = outv[base];
#pragma unroll
        for (int jj = 1; jj < L; jj++) m = fmaxf(m, outv[base + jj]);
        float ssum = 0.0f, dy = 0.0f;
#pragma unroll
        for (int jj = 0; jj < L; jj++) {
            float e = __expf(outv[base + jj] - m);
            logits[base + jj] = e;
            ssum += e;
            dy = fmaf(yb[base + jj], outv[base + jj], dy);
        }
        float sinv = 1.0f / ssum;
#pragma unroll
        for (int jj = 0; jj < L; jj++) logits[base + jj] *= sinv;
        loss += m + __logf(ssum) - dy;
        base += L;
    }

    if (lane < 18) out[b * 18 + lane] = logits[lane];
    if (lane == 0) g_loss[b] = loss;
}

// ---------------------------------------------------------------------------
// Kernel 3: deterministic loss reduction
// ---------------------------------------------------------------------------
__global__ void loss_reduce(float* __restrict__ out_loss) {
    __shared__ float s[256];
    float v = 0.0f;
    for (int i = threadIdx.x; i < BB; i += 256) v += g_loss[i];
    s[threadIdx.x] = v;
    __syncthreads();
    for (int o = 128; o > 0; o >>= 1) {
        if (threadIdx.x < o) s[threadIdx.x] += s[threadIdx.x + o];
        __syncthreads();
    }
    if (threadIdx.x == 0) *out_loss = s[0] * (1.0f / (float)BB);
}

// ---------------------------------------------------------------------------
extern "C" void kernel_launch(void* const* d_in, const int* in_sizes, int n_in,
                              void* d_out, int out_size) {
    const int*   x   = (const int*)  d_in[0];
    const float* y   = (const float*)d_in[1];
    const float* emb = (const float*)d_in[2];
    const float* aw  = (const float*)d_in[3];
    const float* ab  = (const float*)d_in[4];
    const float* W0  = (const float*)d_in[5];
    const float* W1  = (const float*)d_in[6];
    const float* W2  = (const float*)d_in[7];
    const float* W3  = (const float*)d_in[8];
    const float* W4  = (const float*)d_in[9];
    float* out = (float*)d_out;

    proj_kernel<<<(VV + 63) / 64, 128>>>(emb, aw, ab, W0, W1, W2, W3, W4);
    main_kernel<<<BB / 2, 128>>>(x, y, out);
    loss_reduce<<<1, 256>>>(out + (out_size - 1));
}

// round 15
// speedup vs baseline: 1.8373x; 1.0839x over previous
#include <cuda_runtime.h>
#include <cuda_fp16.h>
#include <math.h>

#define BB 4096
#define SS 200
#define DD 64
#define VV 100000
#define ROWH 32      // halfs per g_proj row (64B stride): g[5], q[18], pad
#define ASTRIDE 72   // halfs per staged smem row (144B) -> conflict-free frags
#define MSTRIDE 12   // floats per staged main row (48B) -> perfect bank tiling

// Static device scratch (allocation-free per harness rules)
__device__ __align__(128) __half g_proj[(size_t)VV * ROWH];
__device__ float g_loss[BB];

__device__ __forceinline__ float fast_tanh(float x) {
    float ax = fabsf(x);
    float t  = __expf(-2.0f * ax);
    float r  = __fdividef(1.0f - t, 1.0f + t);
    return copysignf(r, x);
}

__device__ __forceinline__ void mma_16816(float* c, const unsigned* a, const unsigned* b) {
    asm volatile(
        "mma.sync.aligned.m16n8k16.row.col.f32.f16.f16.f32 "
        "{%0,%1,%2,%3}, {%4,%5,%6,%7}, {%8,%9}, {%0,%1,%2,%3};\n"
        : "+f"(c[0]), "+f"(c[1]), "+f"(c[2]), "+f"(c[3])
        : "r"(a[0]), "r"(a[1]), "r"(a[2]), "r"(a[3]), "r"(b[0]), "r"(b[1]));
}

// ---------------------------------------------------------------------------
// Kernel 1: per-vocab precompute via tensor cores (R12 measured-best shape:
// 128 rows/block, 256 threads, 8 warps x 16 rows).
// ---------------------------------------------------------------------------
__global__ void __launch_bounds__(256)
proj_kernel(const float* __restrict__ emb,
            const float* __restrict__ aw,  const float* __restrict__ ab,
            const float* __restrict__ W0,  const float* __restrict__ W1,
            const float* __restrict__ W2,  const float* __restrict__ W3,
            const float* __restrict__ W4) {
    __shared__ __half semb[128 * ASTRIDE];   // 18432 B
    __shared__ __half sU[24 * ASTRIDE];      //  3456 B
    __shared__ float  sab[5];
    const int tid  = threadIdx.x;
    const int lane = tid & 31;
    const int wid  = tid >> 5;

    // ---- stage U (weights) as fp16: rows j=0..22, row 23 = 0 ----
    for (int e = tid; e < 24 * 64; e += 256) {
        int j = e >> 6, d = e & 63;
        float val = 0.0f;
        if (j < 5) {
            val = aw[j * 64 + d];
        } else if (j < 23) {
            int jq = j - 5;
            const float* Wsrc; int row;
            if      (jq < 2)  { Wsrc = W0; row = jq;      }
            else if (jq < 6)  { Wsrc = W1; row = jq - 2;  }
            else if (jq < 10) { Wsrc = W2; row = jq - 6;  }
            else if (jq < 12) { Wsrc = W3; row = jq - 10; }
            else              { Wsrc = W4; row = jq - 12; }
            val = Wsrc[row * 64 + d];
        }
        sU[j * ASTRIDE + d] = __float2half(val);
    }
    if (tid < 5) sab[tid] = ab[tid];

    // ---- stage emb tile: 128 rows x 16 float4-chunks, coalesced, cvt fp16 ----
    const int base = blockIdx.x * 128;
#pragma unroll
    for (int i = 0; i < 8; i++) {
        int q = i * 256 + tid;           // chunk id in tile
        int r = q >> 4;                  // local row
        int c = q & 15;                  // float4 chunk within row
        int gr = base + r;
        if (gr >= VV) gr = VV - 1;       // clamp (duplicate read, stores guarded)
        float4 v4 = *(const float4*)(emb + (size_t)gr * DD + c * 4);
        __half2 h0 = __floats2half2_rn(v4.x, v4.y);
        __half2 h1 = __floats2half2_rn(v4.z, v4.w);
        uint2 pk = make_uint2(*(unsigned*)&h0, *(unsigned*)&h1);
        *(uint2*)(semb + r * ASTRIDE + c * 4) = pk;
    }
    __syncthreads();

    // ---- load B fragments into registers ----
    unsigned bfr[3][4][2];
    {
        const int bn = lane >> 2;
        const int bk = (lane & 3) * 2;
#pragma unroll
        for (int nt = 0; nt < 3; nt++) {
            int n = nt * 8 + bn;
#pragma unroll
            for (int kt = 0; kt < 4; kt++) {
                bfr[nt][kt][0] = *(const unsigned*)(sU + n * ASTRIDE + kt * 16 + bk);
                bfr[nt][kt][1] = *(const unsigned*)(sU + n * ASTRIDE + kt * 16 + 8 + bk);
            }
        }
    }

    // ---- MMA: warp computes rows [wid*16, wid*16+16) ----
    const int mrow = wid * 16 + (lane >> 2);
    const int ak   = (lane & 3) * 2;
    float cacc[3][4];
#pragma unroll
    for (int nt = 0; nt < 3; nt++)
#pragma unroll
        for (int i = 0; i < 4; i++) cacc[nt][i] = 0.0f;

#pragma unroll
    for (int kt = 0; kt < 4; kt++) {
        unsigned a[4];
        a[0] = *(const unsigned*)(semb + mrow * ASTRIDE + kt * 16 + ak);
        a[1] = *(const unsigned*)(semb + (mrow + 8) * ASTRIDE + kt * 16 + ak);
        a[2] = *(const unsigned*)(semb + mrow * ASTRIDE + kt * 16 + 8 + ak);
        a[3] = *(const unsigned*)(semb + (mrow + 8) * ASTRIDE + kt * 16 + 8 + ak);
#pragma unroll
        for (int nt = 0; nt < 3; nt++)
            mma_16816(cacc[nt], a, bfr[nt][kt]);
    }

    // ---- epilogue: transform j<5, pack fp16, store ----
    const int vbase = base + wid * 16 + (lane >> 2);
#pragma unroll
    for (int h = 0; h < 2; h++) {
        int v = vbase + h * 8;
        if (v < VV) {
#pragma unroll
            for (int nt = 0; nt < 3; nt++) {
                int j0 = nt * 8 + (lane & 3) * 2;
                float x0 = cacc[nt][h * 2 + 0];
                float x1 = cacc[nt][h * 2 + 1];
                if (j0 < 5)     x0 = __expf(fast_tanh(x0 + sab[j0]));
                if (j0 + 1 < 5) x1 = __expf(fast_tanh(x1 + sab[j0 + 1]));
                __half2 hv = __floats2half2_rn(x0, x1);
                *(__half2*)(g_proj + (size_t)v * ROWH + j0) = hv;
            }
        }
    }
}

// ---------------------------------------------------------------------------
// Kernel 2: main fused kernel. Two warps per batch element (100 rows each).
// cp.async gather in TWO groups (rows 0-63, 64-99): group-A compute overlaps
// group-B arrival. Smem stride 48B/row (12 floats) -> perfect 32-bank tiling,
// 21KB/block -> 8+ resident blocks/SM.
// ---------------------------------------------------------------------------
__global__ void __launch_bounds__(128, 8)
main_kernel(const int*   __restrict__ x,
            const float* __restrict__ y,
            float* __restrict__ out) {
    __shared__ float stage_all[4][100 * MSTRIDE];  // per warp: 100 rows x 48B
    __shared__ int   sidx[4][100];
    __shared__ float partial[2][24];

    const int lane = threadIdx.x & 31;
    const int warp = threadIdx.x >> 5;
    const int bi   = warp >> 1;
    const int half = warp & 1;
    const int b    = blockIdx.x * 2 + bi;
    float* st = stage_all[warp];
    int*   si = sidx[warp];

    // Stage this warp's 100 indices
    const int* xb = x + b * SS + half * 100;
#pragma unroll
    for (int c = 0; c < 4; c++) {
        int loc = c * 32 + lane;
        if (loc < 100) si[loc] = xb[loc];
    }
    __syncwarp();

    // ---- group A: rows 0..63 (192 copies = 6 warp-instr) ----
#pragma unroll
    for (int i = 0; i < 6; i++) {
        int id = i * 32 + lane;          // 0..191
        int row = id / 3;
        int ch  = id - row * 3;
        int v   = si[row];
        const __half* src = g_proj + (size_t)v * ROWH + ch * 8;
        unsigned dst = (unsigned)__cvta_generic_to_shared(st + row * MSTRIDE + ch * 4);
        asm volatile("cp.async.cg.shared.global [%0], [%1], 16;\n"
                     :: "r"(dst), "l"(src) : "memory");
    }
    asm volatile("cp.async.commit_group;\n" ::: "memory");

    // ---- group B: rows 64..99 (108 copies) ----
#pragma unroll
    for (int i = 0; i < 4; i++) {
        int id = 192 + i * 32 + lane;    // 192..319 (guard < 300)
        if (id < 300) {
            int row = id / 3;
            int ch  = id - row * 3;
            int v   = si[row];
            const __half* src = g_proj + (size_t)v * ROWH + ch * 8;
            unsigned dst = (unsigned)__cvta_generic_to_shared(st + row * MSTRIDE + ch * 4);
            asm volatile("cp.async.cg.shared.global [%0], [%1], 16;\n"
                         :: "r"(dst), "l"(src) : "memory");
        }
    }
    asm volatile("cp.async.commit_group;\n" ::: "memory");

    float ls[5] = {0.f, 0.f, 0.f, 0.f, 0.f};
    float acc[18];
#pragma unroll
    for (int j = 0; j < 18; j++) acc[j] = 0.0f;

    // ---- compute: iters 0,1 (rows 0..63) need group A; 2,3 need B ----
#pragma unroll
    for (int it = 0; it < 4; it++) {
        if (it == 0)
            asm volatile("cp.async.wait_group 1;\n" ::: "memory");
        if (it == 2)
            asm volatile("cp.async.wait_group 0;\n" ::: "memory");
        int row = it * 32 + lane;
        if (row < 100) {
            const float* rp = st + row * MSTRIDE;
            float4 cs[3];
            cs[0] = *(const float4*)(rp + 0);
            cs[1] = *(const float4*)(rp + 4);
            cs[2] = *(const float4*)(rp + 8);
            const __half2* h2 = (const __half2*)cs;
            float2 p[12];
#pragma unroll
            for (int i = 0; i < 12; i++) p[i] = __half22float2(h2[i]);
            // p: (g0,g1)(g2,g3)(g4,q0)(q1,q2)(q3,q4)(q5,q6)(q7,q8)(q9,q10)
            //    (q11,q12)(q13,q14)(q15,q16)(q17,pad)
            ls[0] += p[0].x; ls[1] += p[0].y; ls[2] += p[1].x;
            ls[3] += p[1].y; ls[4] += p[2].x;
            acc[0]  = fmaf(p[0].x, p[2].y, acc[0]);
            acc[1]  = fmaf(p[0].x, p[3].x, acc[1]);
            acc[2]  = fmaf(p[0].y, p[3].y, acc[2]);
            acc[3]  = fmaf(p[0].y, p[4].x, acc[3]);
            acc[4]  = fmaf(p[0].y, p[4].y, acc[4]);
            acc[5]  = fmaf(p[0].y, p[5].x, acc[5]);
            acc[6]  = fmaf(p[1].x, p[5].y, acc[6]);
            acc[7]  = fmaf(p[1].x, p[6].x, acc[7]);
            acc[8]  = fmaf(p[1].x, p[6].y, acc[8]);
            acc[9]  = fmaf(p[1].x, p[7].x, acc[9]);
            acc[10] = fmaf(p[1].y, p[7].y, acc[10]);
            acc[11] = fmaf(p[1].y, p[8].x, acc[11]);
            acc[12] = fmaf(p[2].x, p[8].y, acc[12]);
            acc[13] = fmaf(p[2].x, p[9].x, acc[13]);
            acc[14] = fmaf(p[2].x, p[9].y, acc[14]);
            acc[15] = fmaf(p[2].x, p[10].x, acc[15]);
            acc[16] = fmaf(p[2].x, p[10].y, acc[16]);
            acc[17] = fmaf(p[2].x, p[11].x, acc[17]);
        }
    }

    // ---- intra-warp reductions ----
#pragma unroll
    for (int k = 0; k < 5; k++) {
#pragma unroll
        for (int o = 16; o > 0; o >>= 1)
            ls[k] += __shfl_xor_sync(0xffffffffu, ls[k], o);
    }
#pragma unroll
    for (int j = 0; j < 18; j++) {
#pragma unroll
        for (int o = 16; o > 0; o >>= 1)
            acc[j] += __shfl_xor_sync(0xffffffffu, acc[j], o);
    }

    // ---- combine halves via smem ----
    if (half == 1) {
        if (lane < 5)  partial[bi][lane] = ls[lane];
        if (lane < 18) partial[bi][5 + lane] = acc[lane];
    }
    __syncthreads();
    if (half == 1) return;

#pragma unroll
    for (int k = 0; k < 5; k++) ls[k] += partial[bi][k];
#pragma unroll
    for (int j = 0; j < 18; j++) acc[j] += partial[bi][5 + j];

    float inv[5];
#pragma unroll
    for (int k = 0; k < 5; k++) inv[k] = 1.0f / ls[k];

    const int kmap[18] = {0,0, 1,1,1,1, 2,2,2,2, 3,3, 4,4,4,4,4,4};
    float outv[18];
#pragma unroll
    for (int j = 0; j < 18; j++) outv[j] = acc[j] * inv[kmap[j]];

    // ---- per-group softmax + cross-entropy loss ----
    const float* yb = y + b * 18;
    const int AL[5] = {2, 4, 4, 2, 6};
    float loss = 0.0f;
    float logits[18];
    int base = 0;
#pragma unroll
    for (int i = 0; i < 5; i++) {
        const int L = AL[i];
        float m = outv[base];
#pragma unroll
        for (int jj = 1; jj < L; jj++) m = fmaxf(m, outv[base + jj]);
        float ssum = 0.0f, dy = 0.0f;
#pragma unroll
        for (int jj = 0; jj < L; jj++) {
            float e = __expf(outv[base + jj] - m);
            logits[base + jj] = e;
            ssum += e;
            dy = fmaf(yb[base + jj], outv[base + jj], dy);
        }
        float sinv = 1.0f / ssum;
#pragma unroll
        for (int jj = 0; jj < L; jj++) logits[base + jj] *= sinv;
        loss += m + __logf(ssum) - dy;
        base += L;
    }

    if (lane < 18) out[b * 18 + lane] = logits[lane];
    if (lane == 0) g_loss[b] = loss;
}

// ---------------------------------------------------------------------------
// Kernel 3: deterministic loss reduction
// ---------------------------------------------------------------------------
__global__ void loss_reduce(float* __restrict__ out_loss) {
    __shared__ float s[256];
    float v = 0.0f;
    for (int i = threadIdx.x; i < BB; i += 256) v += g_loss[i];
    s[threadIdx.x] = v;
    __syncthreads();
    for (int o = 128; o > 0; o >>= 1) {
        if (threadIdx.x < o) s[threadIdx.x] += s[threadIdx.x + o];
        __syncthreads();
    }
    if (threadIdx.x == 0) *out_loss = s[0] * (1.0f / (float)BB);
}

// ---------------------------------------------------------------------------
extern "C" void kernel_launch(void* const* d_in, const int* in_sizes, int n_in,
                              void* d_out, int out_size) {
    const int*   x   = (const int*)  d_in[0];
    const float* y   = (const float*)d_in[1];
    const float* emb = (const float*)d_in[2];
    const float* aw  = (const float*)d_in[3];
    const float* ab  = (const float*)d_in[4];
    const float* W0  = (const float*)d_in[5];
    const float* W1  = (const float*)d_in[6];
    const float* W2  = (const float*)d_in[7];
    const float* W3  = (const float*)d_in[8];
    const float* W4  = (const float*)d_in[9];
    float* out = (float*)d_out;

    proj_kernel<<<(VV + 127) / 128, 256>>>(emb, aw, ab, W0, W1, W2, W3, W4);
    main_kernel<<<BB / 2, 128>>>(x, y, out);
    loss_reduce<<<1, 256>>>(out + (out_size - 1));
}